// round 2
// baseline (speedup 1.0000x reference)
#include <cuda_runtime.h>
#include <cuda_bf16.h>
#include <cstdint>

// ---------------------------------------------------------------------------
// KNN: Q=1024 queries (512-dim), N=50000 data points, k=10, 100 classes.
// score[q][n] = ||d_n||^2 - 2*x_q.d_n   (monotone in L2 distance for fixed q)
// Phase 1: d2[n]         (row norms of data)
// Phase 2: fp32 tiled GEMM -> scores matrix in __device__ scratch
// Phase 3: per-query top-10 (stable, index tie-break) + mode -> out[q]
//
// NOTE: targets is int32 on device (JAX x64 disabled downcasts the int64
// request), so it is read as const int*.
// ---------------------------------------------------------------------------

#define QDIM 512
#define NMAX 50000
#define QMAX 1024

__device__ float g_scores[(size_t)QMAX * NMAX];   // ~204.8 MB scratch
__device__ float g_d2[NMAX];

// ---------------- Phase 1: row norms ----------------
__global__ void knn_norms_kernel(const float* __restrict__ data, int N) {
    int gtid = blockIdx.x * blockDim.x + threadIdx.x;
    int warp = gtid >> 5;
    int lane = gtid & 31;
    if (warp >= N) return;
    const float4* row = reinterpret_cast<const float4*>(data + (size_t)warp * QDIM);
    float s = 0.f;
#pragma unroll
    for (int i = 0; i < 4; i++) {
        float4 v = row[lane + i * 32];
        s += v.x * v.x + v.y * v.y + v.z * v.z + v.w * v.w;
    }
#pragma unroll
    for (int o = 16; o > 0; o >>= 1) s += __shfl_xor_sync(0xFFFFFFFFu, s, o);
    if (lane == 0) g_d2[warp] = s;
}

// ---------------- Phase 2: tiled fp32 GEMM ----------------
// C[q][n] = sum_k X[q][k] * D[n][k];  tiles 128x128, BK=16, 8x8 per thread.
#define BM 128
#define BN 128
#define BK 16
#define PAD 4

__global__ __launch_bounds__(256, 2) void knn_gemm_kernel(
    const float* __restrict__ X, const float* __restrict__ D, int N) {
    __shared__ float As[BK][BM + PAD];
    __shared__ float Bs[BK][BN + PAD];

    const int tid = threadIdx.x;
    const int qBase = blockIdx.y * BM;
    const int nBase = blockIdx.x * BN;
    const int tx = tid & 15;
    const int ty = tid >> 4;
    const int i0 = ty * 8;
    const int j0 = tx * 8;

    float acc[8][8];
#pragma unroll
    for (int i = 0; i < 8; i++)
#pragma unroll
        for (int j = 0; j < 8; j++) acc[i][j] = 0.f;

    for (int kb = 0; kb < QDIM; kb += BK) {
        // Cooperative loads: 128 rows x 16 cols per tile = 512 float4 per matrix.
#pragma unroll
        for (int p = 0; p < 2; p++) {
            int lin = tid + p * 256;
            int row = lin >> 2;     // 0..127
            int c4  = lin & 3;      // 0..3  (float4 column within BK)
            float4 va = *reinterpret_cast<const float4*>(
                X + (size_t)(qBase + row) * QDIM + kb + c4 * 4);
            As[c4 * 4 + 0][row] = va.x;
            As[c4 * 4 + 1][row] = va.y;
            As[c4 * 4 + 2][row] = va.z;
            As[c4 * 4 + 3][row] = va.w;

            int n = nBase + row;
            float4 vb = make_float4(0.f, 0.f, 0.f, 0.f);
            if (n < N)
                vb = *reinterpret_cast<const float4*>(
                    D + (size_t)n * QDIM + kb + c4 * 4);
            Bs[c4 * 4 + 0][row] = vb.x;
            Bs[c4 * 4 + 1][row] = vb.y;
            Bs[c4 * 4 + 2][row] = vb.z;
            Bs[c4 * 4 + 3][row] = vb.w;
        }
        __syncthreads();

#pragma unroll
        for (int kk = 0; kk < BK; kk++) {
            float a[8], b[8];
            *reinterpret_cast<float4*>(a)     = *reinterpret_cast<float4*>(&As[kk][i0]);
            *reinterpret_cast<float4*>(a + 4) = *reinterpret_cast<float4*>(&As[kk][i0 + 4]);
            *reinterpret_cast<float4*>(b)     = *reinterpret_cast<float4*>(&Bs[kk][j0]);
            *reinterpret_cast<float4*>(b + 4) = *reinterpret_cast<float4*>(&Bs[kk][j0 + 4]);
#pragma unroll
            for (int i = 0; i < 8; i++)
#pragma unroll
                for (int j = 0; j < 8; j++) acc[i][j] = fmaf(a[i], b[j], acc[i][j]);
        }
        __syncthreads();
    }

    // Epilogue: score = d2[n] - 2*dot
#pragma unroll
    for (int i = 0; i < 8; i++) {
        int q = qBase + i0 + i;
        float* orow = g_scores + (size_t)q * NMAX;
#pragma unroll
        for (int j = 0; j < 8; j++) {
            int n = nBase + j0 + j;
            if (n < N) orow[n] = g_d2[n] - 2.0f * acc[i][j];
        }
    }
}

// ---------------- Phase 3: per-query top-10 + mode ----------------
#define TK 10
#define TPB 256
#define BIGF 3.402823466e+38f

__global__ __launch_bounds__(TPB) void knn_topk_kernel(
    const int* __restrict__ targets, float* __restrict__ out, int N) {
    __shared__ float ss[TPB][TK + 1];
    __shared__ int   si[TPB][TK + 1];

    const int q = blockIdx.x;
    const int tid = threadIdx.x;
    const float* row = g_scores + (size_t)q * NMAX;

    float bs[TK];
    int   bi[TK];
#pragma unroll
    for (int j = 0; j < TK; j++) { bs[j] = BIGF; bi[j] = 0x7FFFFFFF; }

    // Strided scan in increasing index order => strict '<' insertion preserves
    // the smallest-index-first tie-break of lax.top_k.
    for (int n = tid; n < N; n += TPB) {
        float s = row[n];
        if (s < bs[TK - 1]) {
            float cs = s; int ci = n;
#pragma unroll
            for (int j = 0; j < TK; j++) {
                if (cs < bs[j]) {
                    float tf = bs[j]; int ti = bi[j];
                    bs[j] = cs; bi[j] = ci;
                    cs = tf; ci = ti;
                }
            }
        }
    }

#pragma unroll
    for (int j = 0; j < TK; j++) { ss[tid][j] = bs[j]; si[tid][j] = bi[j]; }
    ss[tid][TK] = BIGF;
    si[tid][TK] = 0x7FFFFFFF;

    // log2 tree merge of sorted 10-lists, lexicographic (score, index).
    for (int stride = TPB / 2; stride > 0; stride >>= 1) {
        __syncthreads();
        if (tid < stride) {
            int ia = 0, ib = 0;
            float os[TK]; int oi[TK];
#pragma unroll
            for (int t = 0; t < TK; t++) {
                float va = ss[tid][ia],          vb = ss[tid + stride][ib];
                int   xa = si[tid][ia],          xb = si[tid + stride][ib];
                bool takeA = (va < vb) || (va == vb && xa < xb);
                if (takeA) { os[t] = va; oi[t] = xa; ia++; }
                else       { os[t] = vb; oi[t] = xb; ib++; }
            }
#pragma unroll
            for (int t = 0; t < TK; t++) { ss[tid][t] = os[t]; si[tid][t] = oi[t]; }
        }
    }

    if (tid == 0) {
        int lab[TK];
#pragma unroll
        for (int t = 0; t < TK; t++) lab[t] = targets[si[0][t]];
        int bestLab = 1 << 30, bestCnt = 0;
#pragma unroll
        for (int i = 0; i < TK; i++) {
            int c = 0;
#pragma unroll
            for (int j = 0; j < TK; j++) c += (lab[j] == lab[i]) ? 1 : 0;
            if (c > bestCnt || (c == bestCnt && lab[i] < bestLab)) {
                bestCnt = c; bestLab = lab[i];
            }
        }
        out[q] = (float)bestLab;
    }
}

// ---------------------------------------------------------------------------
extern "C" void kernel_launch(void* const* d_in, const int* in_sizes, int n_in,
                              void* d_out, int out_size) {
    const float* X       = (const float*)d_in[0];    // [1024, 512]
    const float* data    = (const float*)d_in[1];    // [50000, 512]
    const int*   targets = (const int*)d_in[2];      // [50000] int32 (JAX x64 off)
    float*       out     = (float*)d_out;            // [1024]

    const int N = in_sizes[2];             // 50000
    const int Q = in_sizes[0] / QDIM;      // 1024

    // Phase 1: row norms (one warp per row)
    int norm_threads = 256;
    int norm_blocks  = (N * 32 + norm_threads - 1) / norm_threads;
    knn_norms_kernel<<<norm_blocks, norm_threads>>>(data, N);

    // Phase 2: GEMM -> scores
    dim3 grid((N + BN - 1) / BN, Q / BM);
    knn_gemm_kernel<<<grid, 256>>>(X, data, N);

    // Phase 3: top-10 + mode
    knn_topk_kernel<<<Q, TPB>>>(targets, out, N);
}

// round 3
// speedup vs baseline: 2.3413x; 2.3413x over previous
#include <cuda_runtime.h>
#include <cuda_bf16.h>
#include <cstdint>

// ---------------------------------------------------------------------------
// KNN via candidate-refine:
//   P1: d2[n] row norms (fp32)
//   P2: convert X/data -> bf16 scratch
//   P3: bf16 mma.sync GEMM -> approx scores (fp32, g_scores)
//   P4: per-query approx top-16 candidates
//   P5: exact fp32 rescoring of 16 candidates -> top-10 -> mode -> out
// targets is int32 on device (JAX x64 disabled).
// ---------------------------------------------------------------------------

#define QDIM 512
#define NMAX 50000
#define QMAX 1024
#define NCAND 16

__device__ float         g_scores[(size_t)QMAX * NMAX]; // approx scores
__device__ float         g_d2[NMAX];
__device__ __nv_bfloat16 g_xBF[(size_t)QMAX * QDIM];
__device__ __nv_bfloat16 g_dataBF[(size_t)NMAX * QDIM];
__device__ int           g_cand[QMAX * NCAND];

// ---------------- Phase 1: row norms (fp32) ----------------
__global__ void knn_norms_kernel(const float* __restrict__ data, int N) {
    int gtid = blockIdx.x * blockDim.x + threadIdx.x;
    int warp = gtid >> 5;
    int lane = gtid & 31;
    if (warp >= N) return;
    const float4* row = reinterpret_cast<const float4*>(data + (size_t)warp * QDIM);
    float s = 0.f;
#pragma unroll
    for (int i = 0; i < 4; i++) {
        float4 v = row[lane + i * 32];
        s += v.x * v.x + v.y * v.y + v.z * v.z + v.w * v.w;
    }
#pragma unroll
    for (int o = 16; o > 0; o >>= 1) s += __shfl_xor_sync(0xFFFFFFFFu, s, o);
    if (lane == 0) g_d2[warp] = s;
}

// ---------------- Phase 2: fp32 -> bf16 conversion ----------------
__global__ void knn_convert_kernel(const float* __restrict__ src,
                                   __nv_bfloat16* __restrict__ dst, int n4) {
    int i = blockIdx.x * blockDim.x + threadIdx.x;
    if (i >= n4) return;
    float4 v = reinterpret_cast<const float4*>(src)[i];
    __nv_bfloat162 lo = __float22bfloat162_rn(make_float2(v.x, v.y));
    __nv_bfloat162 hi = __float22bfloat162_rn(make_float2(v.z, v.w));
    uint2 packed;
    packed.x = *reinterpret_cast<uint32_t*>(&lo);
    packed.y = *reinterpret_cast<uint32_t*>(&hi);
    reinterpret_cast<uint2*>(dst)[i] = packed;
}

// ---------------- Phase 3: bf16 MMA GEMM ----------------
// Block tile 128(M) x 128(N), K-chunk 64, 8 warps: warp w -> rows [16w,16w+16).
// Smem rows padded: 64 payload + 8 pad bf16 => stride 72 elems (conflict-free).
#define GBM 128
#define GBN 128
#define GBK 64
#define SSTR 72

__global__ __launch_bounds__(256) void knn_gemm_bf16_kernel(int N) {
    __shared__ __nv_bfloat16 As[GBM * SSTR];
    __shared__ __nv_bfloat16 Bs[GBN * SSTR];

    const int tid   = threadIdx.x;
    const int warp  = tid >> 5;
    const int lane  = tid & 31;
    const int g     = lane >> 2;   // groupID 0..7
    const int t4    = lane & 3;    // 0..3
    const int qBase = blockIdx.y * GBM;
    const int nBase = blockIdx.x * GBN;

    float acc[16][4];
#pragma unroll
    for (int f = 0; f < 16; f++)
#pragma unroll
        for (int c = 0; c < 4; c++) acc[f][c] = 0.f;

    const uint32_t* AsW = reinterpret_cast<const uint32_t*>(As);
    const uint32_t* BsW = reinterpret_cast<const uint32_t*>(Bs);

    for (int kb = 0; kb < QDIM; kb += GBK) {
        // Load 128x64 bf16 tiles: 1024 uint4 per tile, 4 per thread.
#pragma unroll
        for (int p = 0; p < 4; p++) {
            int lin  = tid + p * 256;
            int row  = lin >> 3;       // 0..127
            int c8   = lin & 7;        // uint4 col (8 bf16 each)
            // A (X)
            uint4 va = *reinterpret_cast<const uint4*>(
                g_xBF + (size_t)(qBase + row) * QDIM + kb + c8 * 8);
            *reinterpret_cast<uint4*>(&As[row * SSTR + c8 * 8]) = va;
            // B (data)
            int n = nBase + row;
            uint4 vb = make_uint4(0u, 0u, 0u, 0u);
            if (n < N)
                vb = *reinterpret_cast<const uint4*>(
                    g_dataBF + (size_t)n * QDIM + kb + c8 * 8);
            *reinterpret_cast<uint4*>(&Bs[row * SSTR + c8 * 8]) = vb;
        }
        __syncthreads();

#pragma unroll
        for (int ks = 0; ks < GBK; ks += 16) {
            // A fragment for this warp's 16 rows
            int arow0 = (warp * 16 + g) * (SSTR / 2);
            int arow8 = (warp * 16 + g + 8) * (SSTR / 2);
            int kw    = ks / 2 + t4;
            uint32_t a0 = AsW[arow0 + kw];
            uint32_t a1 = AsW[arow8 + kw];
            uint32_t a2 = AsW[arow0 + kw + 4];
            uint32_t a3 = AsW[arow8 + kw + 4];
#pragma unroll
            for (int f = 0; f < 16; f++) {
                int brow = (f * 8 + g) * (SSTR / 2);
                uint32_t b0 = BsW[brow + kw];
                uint32_t b1 = BsW[brow + kw + 4];
                asm volatile(
                    "mma.sync.aligned.m16n8k16.row.col.f32.bf16.bf16.f32 "
                    "{%0,%1,%2,%3}, {%4,%5,%6,%7}, {%8,%9}, {%0,%1,%2,%3};\n"
                    : "+f"(acc[f][0]), "+f"(acc[f][1]),
                      "+f"(acc[f][2]), "+f"(acc[f][3])
                    : "r"(a0), "r"(a1), "r"(a2), "r"(a3), "r"(b0), "r"(b1));
            }
        }
        __syncthreads();
    }

    // Epilogue: approx score = d2[n] - 2*dot
    int q0 = qBase + warp * 16 + g;
#pragma unroll
    for (int f = 0; f < 16; f++) {
        int n = nBase + f * 8 + t4 * 2;
        if (n < N) {
            float d2a = g_d2[n];
            float d2b = (n + 1 < N) ? g_d2[n + 1] : 0.f;
            float* r0 = g_scores + (size_t)q0 * NMAX + n;
            float* r1 = g_scores + (size_t)(q0 + 8) * NMAX + n;
            r0[0] = d2a - 2.0f * acc[f][0];
            r1[0] = d2a - 2.0f * acc[f][2];
            if (n + 1 < N) {
                r0[1] = d2b - 2.0f * acc[f][1];
                r1[1] = d2b - 2.0f * acc[f][3];
            }
        }
    }
}

// ---------------- Phase 4: approx top-16 candidates ----------------
#define STPB 128
#define BIGF 3.402823466e+38f

__global__ __launch_bounds__(STPB) void knn_select_kernel(int N) {
    __shared__ float ss[STPB][NCAND + 1];
    __shared__ int   si[STPB][NCAND + 1];

    const int q = blockIdx.x;
    const int tid = threadIdx.x;
    const float* row = g_scores + (size_t)q * NMAX;

    float bs[NCAND];
    int   bi[NCAND];
#pragma unroll
    for (int j = 0; j < NCAND; j++) { bs[j] = BIGF; bi[j] = 0x7FFFFFFF; }

    for (int n = tid; n < N; n += STPB) {
        float s = row[n];
        if (s < bs[NCAND - 1]) {
            float cs = s; int ci = n;
#pragma unroll
            for (int j = 0; j < NCAND; j++) {
                if (cs < bs[j]) {
                    float tf = bs[j]; int ti = bi[j];
                    bs[j] = cs; bi[j] = ci;
                    cs = tf; ci = ti;
                }
            }
        }
    }

#pragma unroll
    for (int j = 0; j < NCAND; j++) { ss[tid][j] = bs[j]; si[tid][j] = bi[j]; }
    ss[tid][NCAND] = BIGF;
    si[tid][NCAND] = 0x7FFFFFFF;

    for (int stride = STPB / 2; stride > 0; stride >>= 1) {
        __syncthreads();
        if (tid < stride) {
            int ia = 0, ib = 0;
            float os[NCAND]; int oi[NCAND];
#pragma unroll
            for (int t = 0; t < NCAND; t++) {
                float va = ss[tid][ia],          vb = ss[tid + stride][ib];
                int   xa = si[tid][ia],          xb = si[tid + stride][ib];
                bool takeA = (va < vb) || (va == vb && xa < xb);
                if (takeA) { os[t] = va; oi[t] = xa; ia++; }
                else       { os[t] = vb; oi[t] = xb; ib++; }
            }
#pragma unroll
            for (int t = 0; t < NCAND; t++) { ss[tid][t] = os[t]; si[tid][t] = oi[t]; }
        }
    }
    __syncthreads();
    if (tid < NCAND) g_cand[q * NCAND + tid] = si[0][tid];
}

// ---------------- Phase 5: exact fp32 refine + mode ----------------
#define TK 10

__global__ __launch_bounds__(128) void knn_refine_kernel(
    const float* __restrict__ X, const float* __restrict__ D,
    const int* __restrict__ targets, float* __restrict__ out) {
    __shared__ float rs[NCAND];
    __shared__ int   ri[NCAND];

    const int q = blockIdx.x;
    const int tid = threadIdx.x;
    const int warp = tid >> 5;
    const int lane = tid & 31;

    const float4* X4 = reinterpret_cast<const float4*>(X + (size_t)q * QDIM);

#pragma unroll
    for (int cc = 0; cc < 4; cc++) {
        int c = warp * 4 + cc;
        int n = g_cand[q * NCAND + c];
        const float4* D4 = reinterpret_cast<const float4*>(D + (size_t)n * QDIM);
        float s = 0.f;
#pragma unroll
        for (int j = 0; j < 4; j++) {
            float4 a = X4[lane + j * 32];
            float4 b = D4[lane + j * 32];
            s += a.x * b.x + a.y * b.y + a.z * b.z + a.w * b.w;
        }
#pragma unroll
        for (int o = 16; o > 0; o >>= 1) s += __shfl_xor_sync(0xFFFFFFFFu, s, o);
        if (lane == 0) { rs[c] = g_d2[n] - 2.0f * s; ri[c] = n; }
    }
    __syncthreads();

    if (tid == 0) {
        float sc[NCAND]; int id[NCAND];
#pragma unroll
        for (int i = 0; i < NCAND; i++) { sc[i] = rs[i]; id[i] = ri[i]; }
        int lab[TK];
#pragma unroll
        for (int t = 0; t < TK; t++) {
            int best = -1;
            float bv = BIGF; int bx = 0x7FFFFFFF;
#pragma unroll
            for (int i = 0; i < NCAND; i++) {
                if (sc[i] < bv || (sc[i] == bv && id[i] < bx)) {
                    bv = sc[i]; bx = id[i]; best = i;
                }
            }
            lab[t] = targets[id[best]];
            sc[best] = BIGF; id[best] = 0x7FFFFFFF;
        }
        int bestLab = 1 << 30, bestCnt = 0;
#pragma unroll
        for (int i = 0; i < TK; i++) {
            int c = 0;
#pragma unroll
            for (int j = 0; j < TK; j++) c += (lab[j] == lab[i]) ? 1 : 0;
            if (c > bestCnt || (c == bestCnt && lab[i] < bestLab)) {
                bestCnt = c; bestLab = lab[i];
            }
        }
        out[q] = (float)bestLab;
    }
}

// ---------------------------------------------------------------------------
extern "C" void kernel_launch(void* const* d_in, const int* in_sizes, int n_in,
                              void* d_out, int out_size) {
    const float* X       = (const float*)d_in[0];    // [1024, 512]
    const float* data    = (const float*)d_in[1];    // [50000, 512]
    const int*   targets = (const int*)d_in[2];      // [50000] int32
    float*       out     = (float*)d_out;            // [1024]

    const int N = in_sizes[2];             // 50000
    const int Q = in_sizes[0] / QDIM;      // 1024

    // P1: norms
    int nb = (N * 32 + 255) / 256;
    knn_norms_kernel<<<nb, 256>>>(data, N);

    // P2: bf16 conversion
    __nv_bfloat16 *xbf, *dbf;
    cudaGetSymbolAddress((void**)&xbf, g_xBF);
    cudaGetSymbolAddress((void**)&dbf, g_dataBF);
    int nx4 = Q * QDIM / 4;
    int nd4 = N * QDIM / 4;
    knn_convert_kernel<<<(nx4 + 255) / 256, 256>>>(X, xbf, nx4);
    knn_convert_kernel<<<(nd4 + 255) / 256, 256>>>(data, dbf, nd4);

    // P3: bf16 MMA GEMM -> approx scores
    dim3 grid((N + GBN - 1) / GBN, Q / GBM);
    knn_gemm_bf16_kernel<<<grid, 256>>>(N);

    // P4: approx top-16 candidates
    knn_select_kernel<<<Q, STPB>>>(N);

    // P5: exact refine + mode
    knn_refine_kernel<<<Q, 128>>>(X, data, targets, out);
}